// round 9
// baseline (speedup 1.0000x reference)
#include <cuda_runtime.h>
#include <cuda_fp16.h>
#include <math.h>

#define BATCH 32
#define LDIM  4096
#define MEMD  256
#define NTURN 5
#define CPB   9
#define G_CTAS (BATCH * CPB)        // 288
#define OUT_HALF (BATCH * LDIM)

// ---------------- device scratch ----------------
__device__ uint4 g_Mh[BATCH * LDIM * 32];      // fp16 copy of M (64 MB)
__device__ float g_s[2 * BATCH * MEMD];        // parity double-buffered
__device__ float g_qb[BATCH * MEMD];
__device__ float g_qa[BATCH * MEMD];
__device__ float g_qe[BATCH * MEMD];
__device__ float g_scoreS[2 * BATCH * LDIM];
__device__ float g_scoreE[2 * BATCH * LDIM];
__device__ float g_gmS[BATCH], g_rzS[BATCH], g_gmE[BATCH], g_rzE[BATCH];
__device__ float g_pV1[G_CTAS * MEMD];
__device__ float g_pV2[G_CTAS * MEMD];
__device__ float g_pm1[G_CTAS], g_pz1[G_CTAS], g_pm2[G_CTAS], g_pz2[G_CTAS];
__device__ float g_pmE[G_CTAS], g_pzE[G_CTAS];
__device__ float g_gio[768 * 32];
__device__ float g_gho[768 * 32];

// ---------------- helpers ----------------
__device__ __forceinline__ float dot44(float4 a, float4 x) {
    return a.x * x.x + a.y * x.y + a.z * x.z + a.w * x.w;
}
__device__ __forceinline__ void scale4(float4& v, float s) {
    v.x *= s; v.y *= s; v.z *= s; v.w *= s;
}
__device__ __forceinline__ void fma4(float4& v, float s, float4 x) {
    v.x += s * x.x; v.y += s * x.y; v.z += s * x.z; v.w += s * x.w;
}
__device__ __forceinline__ float dotw(float4 wv, const float* xp) {
    return wv.x * xp[0] + wv.y * xp[1] + wv.z * xp[2] + wv.w * xp[3];
}

// ---------------- init ----------------
__global__ void k_init(float* __restrict__ out, const float* __restrict__ s0, int outn) {
    int i = blockIdx.x * 256 + threadIdx.x;
    if (i < outn) out[i] = 0.0f;
    if (i < BATCH * MEMD) g_s[i] = s0[i];
}
__global__ void k_zero() {   // filler so k_bigc lands at ncu launch index 3
    int i = blockIdx.x * 256 + threadIdx.x;
    if (i < G_CTAS) { g_pmE[i] = -1e30f; g_pzE[i] = 0.f; }
}

// ---------------- P0: fp32 pass + fp16 conversion ----------------
__global__ void __launch_bounds__(256, 2)
k_bigc(const float* __restrict__ M) {
    __shared__ float cV1[8 * MEMD], cV2[8 * MEMD];
    __shared__ float cm1[8], cz1[8], cm2[8], cz2[8];

    const int b  = blockIdx.x / CPB;
    const int cb = blockIdx.x % CPB;
    const int rs = (cb * LDIM) / CPB;
    const int re = ((cb + 1) * LDIM) / CPB;
    const int t = threadIdx.x, w = t >> 5, k = t & 31;

    float4 z4 = make_float4(0.f, 0.f, 0.f, 0.f);
    const int bo = b * MEMD + 4 * k;
    float4 qb0 = *(const float4*)(g_qb + bo), qb1 = *(const float4*)(g_qb + bo + 128);
    float4 qa0 = *(const float4*)(g_qa + bo), qa1 = *(const float4*)(g_qa + bo + 128);

    const float* Mb = M + (size_t)b * LDIM * MEMD;
    uint2* Mhb = (uint2*)(g_Mh + (size_t)b * LDIM * 32);

    float m1 = -1e30f, z1 = 0.f, m2 = -1e30f, z2 = 0.f;
    float4 V10 = z4, V11 = z4, V20 = z4, V21 = z4;

    for (int r4 = rs + w * 4; r4 < re; r4 += 32) {
        float4 x[4][2];
        #pragma unroll
        for (int i = 0; i < 4; i++) {
            int row = r4 + i; if (row > re - 1) row = re - 1;
            const float4* rp = (const float4*)(Mb + (size_t)row * MEMD);
            x[i][0] = __ldg(rp + k);
            x[i][1] = __ldg(rp + 32 + k);
        }
        #pragma unroll
        for (int i = 0; i < 4; i++) {
            bool valid = (r4 + i) < re;
            if (valid) {
                __half2 h0 = __floats2half2_rn(x[i][0].x, x[i][0].y);
                __half2 h1 = __floats2half2_rn(x[i][0].z, x[i][0].w);
                __half2 h2 = __floats2half2_rn(x[i][1].x, x[i][1].y);
                __half2 h3 = __floats2half2_rn(x[i][1].z, x[i][1].w);
                uint2 u0, u1;
                u0.x = *(unsigned*)&h0; u0.y = *(unsigned*)&h1;
                u1.x = *(unsigned*)&h2; u1.y = *(unsigned*)&h3;
                Mhb[(size_t)(r4 + i) * 64 + k] = u0;
                Mhb[(size_t)(r4 + i) * 64 + 32 + k] = u1;
            }
            float db = dot44(qb0, x[i][0]) + dot44(qb1, x[i][1]);
            float da = dot44(qa0, x[i][0]) + dot44(qa1, x[i][1]);
            #pragma unroll
            for (int off = 16; off; off >>= 1) {
                db += __shfl_xor_sync(~0u, db, off);
                da += __shfl_xor_sync(~0u, da, off);
            }
            if (valid) {
                if (db > m1) {
                    float sc = __expf(m1 - db);
                    z1 *= sc; scale4(V10, sc); scale4(V11, sc); m1 = db;
                }
                float w1 = __expf(db - m1);
                z1 += w1; fma4(V10, w1, x[i][0]); fma4(V11, w1, x[i][1]);
                if (da > m2) {
                    float sc = __expf(m2 - da);
                    z2 *= sc; scale4(V20, sc); scale4(V21, sc); m2 = da;
                }
                float w2 = __expf(da - m2);
                z2 += w2; fma4(V20, w2, x[i][0]); fma4(V21, w2, x[i][1]);
                if (k == i) g_scoreS[b * LDIM + r4 + i] = db;
            }
        }
    }

    *(float4*)(cV1 + w * MEMD + 4 * k)       = V10;
    *(float4*)(cV1 + w * MEMD + 128 + 4 * k) = V11;
    *(float4*)(cV2 + w * MEMD + 4 * k)       = V20;
    *(float4*)(cV2 + w * MEMD + 128 + 4 * k) = V21;
    if (k == 0) { cm1[w] = m1; cz1[w] = z1; cm2[w] = m2; cz2[w] = z2; }
    __syncthreads();
    float a1 = cm1[0], a2 = cm2[0];
    #pragma unroll
    for (int wi = 1; wi < 8; wi++) { a1 = fmaxf(a1, cm1[wi]); a2 = fmaxf(a2, cm2[wi]); }
    float v1 = 0.f, gz1 = 0.f, v2 = 0.f, gz2 = 0.f;
    #pragma unroll
    for (int wi = 0; wi < 8; wi++) {
        float e1 = __expf(cm1[wi] - a1), e2 = __expf(cm2[wi] - a2);
        v1 += e1 * cV1[wi * MEMD + t]; gz1 += e1 * cz1[wi];
        v2 += e2 * cV2[wi * MEMD + t]; gz2 += e2 * cz2[wi];
    }
    int slot = blockIdx.x;
    g_pV1[slot * MEMD + t] = v1;
    g_pV2[slot * MEMD + t] = v2;
    if (t == 0) {
        g_pm1[slot] = a1; g_pz1[slot] = gz1;
        g_pm2[slot] = a2; g_pz2[slot] = gz2;
    }
}

// ---------------- P1..P5: fp16 streaming pass ----------------
__global__ void __launch_bounds__(256, 2)
k_bigh(float* __restrict__ out,
       int doMain, int doEnd, int accS, int accE, int sW, int eW) {
    __shared__ float cV1[8 * MEMD], cV2[8 * MEMD];
    __shared__ float cm1[8], cz1[8], cm2[8], cz2[8], cmE[8], czE[8];

    const int b  = blockIdx.x / CPB;
    const int cb = blockIdx.x % CPB;
    const int rs = (cb * LDIM) / CPB;
    const int re = ((cb + 1) * LDIM) / CPB;
    const int t = threadIdx.x, w = t >> 5, k = t & 31;

    float4 z4 = make_float4(0.f, 0.f, 0.f, 0.f);
    float4 qb0 = z4, qb1 = z4, qa0 = z4, qa1 = z4, qe0 = z4, qe1 = z4;
    const int bo = b * MEMD + 8 * k;
    if (doMain) {
        qb0 = *(const float4*)(g_qb + bo); qb1 = *(const float4*)(g_qb + bo + 4);
        qa0 = *(const float4*)(g_qa + bo); qa1 = *(const float4*)(g_qa + bo + 4);
    }
    if (doEnd) {
        qe0 = *(const float4*)(g_qe + bo); qe1 = *(const float4*)(g_qe + bo + 4);
    }
    float gmS = 0.f, rzS = 0.f, gmE = 0.f, rzE = 0.f;
    if (accS) { gmS = g_gmS[b]; rzS = g_rzS[b]; }
    if (accE) { gmE = g_gmE[b]; rzE = g_rzE[b]; }
    float* sWr = g_scoreS + (size_t)sW * OUT_HALF;
    const float* sRd = g_scoreS + (size_t)(1 - sW) * OUT_HALF;
    float* eWr = g_scoreE + (size_t)eW * OUT_HALF;
    const float* eRd = g_scoreE + (size_t)(1 - eW) * OUT_HALF;

    const uint4* Mhb = g_Mh + (size_t)b * LDIM * 32;

    float m1 = -1e30f, z1 = 0.f, m2 = -1e30f, z2 = 0.f, mE = -1e30f, zE = 0.f;
    float4 V10 = z4, V11 = z4, V20 = z4, V21 = z4;

    for (int r8 = rs + w * 8; r8 < re; r8 += 64) {
        uint4 xr[8];
        #pragma unroll
        for (int i = 0; i < 8; i++) {
            int row = r8 + i; if (row > re - 1) row = re - 1;
            xr[i] = __ldg(Mhb + (size_t)row * 32 + k);
        }
        #pragma unroll
        for (int i = 0; i < 8; i++) {
            bool valid = (r8 + i) < re;
            const __half2* h = (const __half2*)&xr[i];
            float2 f0 = __half22float2(h[0]);
            float2 f1 = __half22float2(h[1]);
            float2 f2 = __half22float2(h[2]);
            float2 f3 = __half22float2(h[3]);
            float4 x0 = make_float4(f0.x, f0.y, f1.x, f1.y);
            float4 x1 = make_float4(f2.x, f2.y, f3.x, f3.y);
            float db = 0.f, da = 0.f, de = 0.f;
            if (doMain) {
                db = dot44(qb0, x0) + dot44(qb1, x1);
                da = dot44(qa0, x0) + dot44(qa1, x1);
            }
            if (doEnd) de = dot44(qe0, x0) + dot44(qe1, x1);
            #pragma unroll
            for (int off = 16; off; off >>= 1) {
                db += __shfl_xor_sync(~0u, db, off);
                da += __shfl_xor_sync(~0u, da, off);
                de += __shfl_xor_sync(~0u, de, off);
            }
            if (doMain && valid) {
                if (db > m1) {
                    float sc = __expf(m1 - db);
                    z1 *= sc; scale4(V10, sc); scale4(V11, sc); m1 = db;
                }
                float w1 = __expf(db - m1);
                z1 += w1; fma4(V10, w1, x0); fma4(V11, w1, x1);
                if (da > m2) {
                    float sc = __expf(m2 - da);
                    z2 *= sc; scale4(V20, sc); scale4(V21, sc); m2 = da;
                }
                float w2 = __expf(da - m2);
                z2 += w2; fma4(V20, w2, x0); fma4(V21, w2, x1);
            }
            if (doEnd && valid) {
                if (de > mE) { zE *= __expf(mE - de); mE = de; }
                zE += __expf(de - mE);
            }
            if (valid) {
                int idx = b * LDIM + r8 + i;
                if (k == i) {
                    if (doMain) sWr[idx] = db;
                    if (doEnd)  eWr[idx] = de;
                }
                if (accS && k == 8 + i)
                    out[idx] += __expf(__ldg(sRd + idx) - gmS) * rzS;
                if (accE && k == 16 + i)
                    out[OUT_HALF + idx] += __expf(__ldg(eRd + idx) - gmE) * rzE;
            }
        }
    }

    if (k == 0) {
        cm1[w] = m1; cz1[w] = z1; cm2[w] = m2; cz2[w] = z2;
        cmE[w] = mE; czE[w] = zE;
    }
    if (doMain) {
        *(float4*)(cV1 + w * MEMD + 8 * k)     = V10;
        *(float4*)(cV1 + w * MEMD + 8 * k + 4) = V11;
        *(float4*)(cV2 + w * MEMD + 8 * k)     = V20;
        *(float4*)(cV2 + w * MEMD + 8 * k + 4) = V21;
    }
    __syncthreads();
    int slot = blockIdx.x;
    if (doMain) {
        float a1 = cm1[0], a2 = cm2[0];
        #pragma unroll
        for (int wi = 1; wi < 8; wi++) { a1 = fmaxf(a1, cm1[wi]); a2 = fmaxf(a2, cm2[wi]); }
        float v1 = 0.f, gz1 = 0.f, v2 = 0.f, gz2 = 0.f;
        #pragma unroll
        for (int wi = 0; wi < 8; wi++) {
            float e1 = __expf(cm1[wi] - a1), e2 = __expf(cm2[wi] - a2);
            v1 += e1 * cV1[wi * MEMD + t]; gz1 += e1 * cz1[wi];
            v2 += e2 * cV2[wi * MEMD + t]; gz2 += e2 * cz2[wi];
        }
        g_pV1[slot * MEMD + t] = v1;
        g_pV2[slot * MEMD + t] = v2;
        if (t == 0) {
            g_pm1[slot] = a1; g_pz1[slot] = gz1;
            g_pm2[slot] = a2; g_pz2[slot] = gz2;
        }
    }
    if (doEnd && t == 0) {
        float aE = cmE[0];
        #pragma unroll
        for (int wi = 1; wi < 8; wi++) aE = fmaxf(aE, cmE[wi]);
        float gzE = 0.f;
        #pragma unroll
        for (int wi = 0; wi < 8; wi++) gzE += __expf(cmE[wi] - aE) * czE[wi];
        g_pmE[slot] = aE; g_pzE[slot] = gzE;
    }
}

// ---------------- fused gemv: (mid merge) + qe/gio/gho with smem-staged weights ----------------
// grid 56, 256 thr. CTA 0-7: qe rows (We, K=512, inputs s|endvec).
// CTA 8-31: W_ih rows 0..767 (input x1). CTA 32-55: W_hh rows 0..767 (input s).
__global__ void __launch_bounds__(256)
k_gemv2(const float* __restrict__ We,
        const float* __restrict__ W_ih,
        const float* __restrict__ W_hh,
        const float* __restrict__ b_ih,
        const float* __restrict__ b_hh,
        int hasE, int sp) {
    extern __shared__ float smg[];
    float* xs = smg;                  // 32*257
    float* es = smg + 8224;           // 32*257 (seg0 only)
    float* ws = smg + 16448;          // 8192 staged weights
    __shared__ float wg[32 * 10];

    const int cta = blockIdx.x, t = threadIdx.x, w = t >> 5, lane = t & 31;
    const int seg = (cta < 8) ? 0 : (cta < 32 ? 1 : 2);
    const float* sbase = g_s + sp * (BATCH * MEMD);

    // per-batch merge weights (seg0 from pm1/pz1, seg1 from pm2/pz2)
    if (t < 32 && seg != 2) {
        int b = t;
        const float* pm = (seg == 0) ? g_pm1 : g_pm2;
        const float* pz = (seg == 0) ? g_pz1 : g_pz2;
        float m = -1e30f;
        #pragma unroll
        for (int c = 0; c < CPB; c++) m = fmaxf(m, pm[b * CPB + c]);
        float Z = 0.f;
        #pragma unroll
        for (int c = 0; c < CPB; c++) {
            float e = __expf(pm[b * CPB + c] - m);
            wg[b * 10 + c] = e;
            Z += e * pz[b * CPB + c];
        }
        wg[b * 10 + 9] = 1.f / Z;
        if (cta == 0) {
            g_gmS[b] = m; g_rzS[b] = 1.f / Z;   // seg0: S stats
            if (hasE) {
                float mE = -1e30f;
                #pragma unroll
                for (int c = 0; c < CPB; c++) mE = fmaxf(mE, g_pmE[b * CPB + c]);
                float ZE = 0.f;
                #pragma unroll
                for (int c = 0; c < CPB; c++) ZE += __expf(g_pmE[b * CPB + c] - mE) * g_pzE[b * CPB + c];
                g_gmE[b] = mE; g_rzE[b] = 1.f / ZE;
            }
        }
    }
    __syncthreads();

    // input vectors
    if (seg == 0) {
        for (int i = t; i < BATCH * MEMD; i += 256) {
            int b = i >> 8, j = i & 255;
            xs[b * 257 + j] = sbase[i];
            float v = 0.f;
            #pragma unroll
            for (int c = 0; c < CPB; c++)
                v += wg[b * 10 + c] * g_pV1[(b * CPB + c) * MEMD + j];
            es[b * 257 + j] = v * wg[b * 10 + 9];
        }
    } else if (seg == 1) {
        for (int i = t; i < BATCH * MEMD; i += 256) {
            int b = i >> 8, j = i & 255;
            float v = 0.f;
            #pragma unroll
            for (int c = 0; c < CPB; c++)
                v += wg[b * 10 + c] * g_pV2[(b * CPB + c) * MEMD + j];
            xs[b * 257 + j] = v * wg[b * 10 + 9];
        }
    } else {
        for (int i = t; i < BATCH * MEMD; i += 256)
            xs[(i >> 8) * 257 + (i & 255)] = sbase[i];
    }
    __syncthreads();

    const float* xrow = &xs[lane * 257];
    const float* erow = &es[lane * 257];
    const float4* ws4 = (const float4*)ws;

    if (seg == 0) {
        // 2 chunks of 16 rows x 512 floats
        int base = cta * 32;
        for (int ch = 0; ch < 2; ch++) {
            for (int i = t; i < 8192; i += 256)
                ws[i] = We[(size_t)(base + ch * 16 + (i >> 9)) * 512 + (i & 511)];
            __syncthreads();
            #pragma unroll
            for (int rr = 0; rr < 2; rr++) {
                int lr = w * 2 + rr;
                int r = base + ch * 16 + lr;
                const float4* W0 = ws4 + lr * 128;
                float a0 = 0.f, a1 = 0.f, a2 = 0.f, a3 = 0.f;
                #pragma unroll
                for (int k4 = 0; k4 < 64; k4 += 4) {
                    a0 += dotw(W0[k4],     xrow + k4 * 4);
                    a1 += dotw(W0[k4 + 1], xrow + k4 * 4 + 4);
                    a2 += dotw(W0[k4 + 2], xrow + k4 * 4 + 8);
                    a3 += dotw(W0[k4 + 3], xrow + k4 * 4 + 12);
                }
                #pragma unroll
                for (int k4 = 0; k4 < 64; k4 += 4) {
                    a0 += dotw(W0[64 + k4],     erow + k4 * 4);
                    a1 += dotw(W0[64 + k4 + 1], erow + k4 * 4 + 4);
                    a2 += dotw(W0[64 + k4 + 2], erow + k4 * 4 + 8);
                    a3 += dotw(W0[64 + k4 + 3], erow + k4 * 4 + 12);
                }
                g_qe[lane * MEMD + r] = (a0 + a1) + (a2 + a3);
            }
            __syncthreads();
        }
    } else {
        const float* W = (seg == 1) ? W_ih : W_hh;
        const float* bias = (seg == 1) ? b_ih : b_hh;
        float* gout = (seg == 1) ? g_gio : g_gho;
        int base = ((seg == 1) ? (cta - 8) : (cta - 32)) * 32;
        for (int i = t; i < 8192; i += 256)
            ws[i] = W[(size_t)(base + (i >> 8)) * 256 + (i & 255)];
        __syncthreads();
        #pragma unroll
        for (int rr = 0; rr < 4; rr++) {
            int lr = w * 4 + rr;
            int ri = base + lr;
            const float4* W0 = ws4 + lr * 64;
            float a0 = __ldg(bias + ri), a1 = 0.f, a2 = 0.f, a3 = 0.f;
            #pragma unroll
            for (int k4 = 0; k4 < 64; k4 += 4) {
                a0 += dotw(W0[k4],     xrow + k4 * 4);
                a1 += dotw(W0[k4 + 1], xrow + k4 * 4 + 4);
                a2 += dotw(W0[k4 + 2], xrow + k4 * 4 + 8);
                a3 += dotw(W0[k4 + 3], xrow + k4 * 4 + 12);
            }
            gout[ri * 32 + lane] = (a0 + a1) + (a2 + a3);
        }
    }
}

// ---------------- fused GRU + vm2 (qb/qa) with staged weights ----------------
// grid 16, 256 thr. Each CTA redundantly computes the full GRU (if doGru)
// into smem + writes new s to parity 1-sp; then computes 32 of the 512 qb|qa rows.
__global__ void __launch_bounds__(256)
k_gruvm2(const float* __restrict__ Wb, const float* __restrict__ Wa,
         int doGru, int sp) {
    extern __shared__ float smg[];
    float* xs = smg;                  // 32*257
    float* ws = smg + 8224;           // 8192
    const int cta = blockIdx.x, t = threadIdx.x, w = t >> 5, lane = t & 31;
    const float* sOld = g_s + sp * (BATCH * MEMD);
    float* sNew = g_s + (1 - sp) * (BATCH * MEMD);

    if (doGru) {
        for (int i = t; i < BATCH * MEMD; i += 256) {
            int col = i >> 5, b = i & 31;
            float gir = g_gio[i], giz = g_gio[8192 + i], gin = g_gio[16384 + i];
            float ghr = g_gho[i], ghz = g_gho[8192 + i], ghn = g_gho[16384 + i];
            float r = 1.0f / (1.0f + __expf(-(gir + ghr)));
            float z = 1.0f / (1.0f + __expf(-(giz + ghz)));
            float n = tanhf(gin + r * ghn);
            float sold = sOld[b * MEMD + col];
            float sv = (1.0f - z) * n + z * sold;
            xs[b * 257 + col] = sv;
            if (cta == 0) sNew[b * MEMD + col] = sv;
        }
    } else {
        for (int i = t; i < BATCH * MEMD; i += 256)
            xs[(i >> 8) * 257 + (i & 255)] = sOld[i];
    }

    // stage this CTA's 32 weight rows
    const float* W = (cta < 8) ? Wb : Wa;
    int base = (cta & 7) * 32;
    for (int i = t; i < 8192; i += 256)
        ws[i] = W[(size_t)(base + (i >> 8)) * 256 + (i & 255)];
    __syncthreads();

    const float* xrow = &xs[lane * 257];
    const float4* ws4 = (const float4*)ws;
    float* outv = (cta < 8) ? g_qb : g_qa;
    #pragma unroll
    for (int rr = 0; rr < 4; rr++) {
        int lr = w * 4 + rr;
        int n = base + lr;
        const float4* W0 = ws4 + lr * 64;
        float a0 = 0.f, a1 = 0.f, a2 = 0.f, a3 = 0.f;
        #pragma unroll
        for (int k4 = 0; k4 < 64; k4 += 4) {
            a0 += dotw(W0[k4],     xrow + k4 * 4);
            a1 += dotw(W0[k4 + 1], xrow + k4 * 4 + 4);
            a2 += dotw(W0[k4 + 2], xrow + k4 * 4 + 8);
            a3 += dotw(W0[k4 + 3], xrow + k4 * 4 + 12);
        }
        outv[lane * MEMD + n] = (a0 + a1) + (a2 + a3);
    }
}

// ---------------- finalize ----------------
__global__ void k_fin(float* __restrict__ out) {
    int which = blockIdx.y, b = blockIdx.x, t = threadIdx.x;
    __shared__ float st[2];
    if (which == 1 && t == 0) {
        float mE = -1e30f;
        #pragma unroll
        for (int cc = 0; cc < CPB; cc++) mE = fmaxf(mE, g_pmE[b * CPB + cc]);
        float ZE = 0.f;
        #pragma unroll
        for (int cc = 0; cc < CPB; cc++) ZE += __expf(g_pmE[b * CPB + cc] - mE) * g_pzE[b * CPB + cc];
        st[0] = mE; st[1] = 1.f / ZE;
    }
    __syncthreads();
    if (which == 0) {
        #pragma unroll
        for (int i = 0; i < 16; i++) {
            int idx = b * LDIM + i * 256 + t;
            out[idx] = logf(out[idx] * (1.0f / NTURN));
        }
    } else {
        float m = st[0], rz = st[1];
        const float* e4 = g_scoreE;   // buffer 0 holds E_4
        #pragma unroll
        for (int i = 0; i < 16; i++) {
            int idx = b * LDIM + i * 256 + t;
            float v = out[OUT_HALF + idx] + __expf(e4[idx] - m) * rz;
            out[OUT_HALF + idx] = logf(v * (1.0f / NTURN));
        }
    }
}

// ---------------- launch ----------------
extern "C" void kernel_launch(void* const* d_in, const int* in_sizes, int n_in,
                              void* d_out, int out_size) {
    (void)in_sizes; (void)n_in;
    const float* M    = (const float*)d_in[0];
    const float* s0   = (const float*)d_in[1];
    const float* Wb   = (const float*)d_in[2];
    const float* We   = (const float*)d_in[3];
    const float* Wa   = (const float*)d_in[4];
    const float* W_ih = (const float*)d_in[5];
    const float* W_hh = (const float*)d_in[6];
    const float* b_ih = (const float*)d_in[7];
    const float* b_hh = (const float*)d_in[8];
    float* out = (float*)d_out;

    const int GE_SMEM = (2 * 8224 + 8192) * 4;   // 98,560 B
    const int GV_SMEM = (8224 + 8192) * 4;       // 65,664 B
    cudaFuncSetAttribute(k_gemv2,  cudaFuncAttributeMaxDynamicSharedMemorySize, GE_SMEM);
    cudaFuncSetAttribute(k_gruvm2, cudaFuncAttributeMaxDynamicSharedMemorySize, GV_SMEM);

    int gblocks = (out_size + 255) / 256;
    if (gblocks < 32) gblocks = 32;
    k_init<<<gblocks, 256>>>(out, s0, out_size);                         // 0
    k_gruvm2<<<16, 256, GV_SMEM>>>(Wb, Wa, 0, 0);                        // 1: qb/qa from s0
    k_zero<<<2, 256>>>();                                                // 2
    // P0: fp32 + convert; S_0, alpha_0
    k_bigc<<<G_CTAS, 256>>>(M);                                          // 3 <-- ncu
    k_gemv2<<<56, 256, GE_SMEM>>>(We, W_ih, W_hh, b_ih, b_hh, 0, 0);
    k_gruvm2<<<16, 256, GV_SMEM>>>(Wb, Wa, 1, 0);
    // P1: S_1, alpha_1, E_0 ; acc S_0
    k_bigh<<<G_CTAS, 256>>>(out, 1, 1, 1, 0, 1, 0);
    k_gemv2<<<56, 256, GE_SMEM>>>(We, W_ih, W_hh, b_ih, b_hh, 1, 1);
    k_gruvm2<<<16, 256, GV_SMEM>>>(Wb, Wa, 1, 1);
    // P2: S_2, E_1 ; acc S_1, E_0
    k_bigh<<<G_CTAS, 256>>>(out, 1, 1, 1, 1, 0, 1);
    k_gemv2<<<56, 256, GE_SMEM>>>(We, W_ih, W_hh, b_ih, b_hh, 1, 0);
    k_gruvm2<<<16, 256, GV_SMEM>>>(Wb, Wa, 1, 0);
    // P3: S_3, E_2 ; acc S_2, E_1
    k_bigh<<<G_CTAS, 256>>>(out, 1, 1, 1, 1, 1, 0);
    k_gemv2<<<56, 256, GE_SMEM>>>(We, W_ih, W_hh, b_ih, b_hh, 1, 1);
    k_gruvm2<<<16, 256, GV_SMEM>>>(Wb, Wa, 1, 1);
    // P4: S_4, E_3 ; acc S_3, E_2
    k_bigh<<<G_CTAS, 256>>>(out, 1, 1, 1, 1, 0, 1);
    k_gemv2<<<56, 256, GE_SMEM>>>(We, W_ih, W_hh, b_ih, b_hh, 1, 0);   // qe_4 + stats
    // P5: E_4 only ; acc S_4 (buf0), E_3 (buf1)
    k_bigh<<<G_CTAS, 256>>>(out, 0, 1, 1, 1, 1, 0);
    k_fin<<<dim3(BATCH, 2), 256>>>(out);
}

// round 10
// speedup vs baseline: 1.0729x; 1.0729x over previous
#include <cuda_runtime.h>
#include <cuda_fp16.h>
#include <math.h>

#define BATCH 32
#define LDIM  4096
#define MEMD  256
#define NTURN 5
#define CPB   9
#define G_CTAS (BATCH * CPB)        // 288
#define OUT_HALF (BATCH * LDIM)

// ---------------- device scratch ----------------
__device__ uint4 g_Mh[BATCH * LDIM * 32];      // fp16 copy of M (64 MB)
__device__ float g_s[2 * BATCH * MEMD];        // parity double-buffered
__device__ float g_qb[BATCH * MEMD];
__device__ float g_qa[BATCH * MEMD];
__device__ float g_qe[BATCH * MEMD];
__device__ float g_scoreS[NTURN * OUT_HALF];   // 5 planes
__device__ float g_scoreE[NTURN * OUT_HALF];
__device__ float g_stSm[NTURN * BATCH], g_stSrz[NTURN * BATCH];
__device__ float g_stEm[NTURN * BATCH], g_stErz[NTURN * BATCH];
__device__ float g_pV1[G_CTAS * MEMD];
__device__ float g_pV2[G_CTAS * MEMD];
__device__ float g_pm1[G_CTAS], g_pz1[G_CTAS], g_pm2[G_CTAS], g_pz2[G_CTAS];
__device__ float g_pmE[G_CTAS], g_pzE[G_CTAS];
__device__ float g_gio[768 * 32];
__device__ float g_gho[768 * 32];
__device__ unsigned g_barrier;

// ---------------- helpers ----------------
__device__ __forceinline__ float dot44(float4 a, float4 x) {
    return a.x * x.x + a.y * x.y + a.z * x.z + a.w * x.w;
}
__device__ __forceinline__ void scale4(float4& v, float s) {
    v.x *= s; v.y *= s; v.z *= s; v.w *= s;
}
__device__ __forceinline__ void fma4(float4& v, float s, float4 x) {
    v.x += s * x.x; v.y += s * x.y; v.z += s * x.z; v.w += s * x.w;
}
__device__ __forceinline__ float dotw(float4 wv, const float* xp) {
    return wv.x * xp[0] + wv.y * xp[1] + wv.z * xp[2] + wv.w * xp[3];
}

// ---------------- init: s0 -> g_s, qb/qa from s0 (staged weights) ----------------
__global__ void __launch_bounds__(256)
k_initvm(const float* __restrict__ s0, const float* __restrict__ Wb,
         const float* __restrict__ Wa) {
    extern __shared__ float smg[];
    float* xs = smg;              // 32*257
    float* ws = smg + 8224;       // 8192
    int cta = blockIdx.x, t = threadIdx.x, w = t >> 5, lane = t & 31;
    for (int i = t; i < BATCH * MEMD; i += 256) {
        xs[(i >> 8) * 257 + (i & 255)] = s0[i];
        if (cta == 0) g_s[i] = s0[i];
    }
    const float* W = (cta < 8) ? Wb : Wa;
    int base = (cta & 7) * 32;
    for (int i = t; i < 8192; i += 256)
        ws[i] = W[(size_t)(base + (i >> 8)) * 256 + (i & 255)];
    __syncthreads();
    const float* xrow = &xs[lane * 257];
    const float4* ws4 = (const float4*)ws;
    float* outv = (cta < 8) ? g_qb : g_qa;
    #pragma unroll
    for (int rr = 0; rr < 4; rr++) {
        int lr = w * 4 + rr;
        const float4* W0 = ws4 + lr * 64;
        float a0 = 0.f, a1 = 0.f, a2 = 0.f, a3 = 0.f;
        #pragma unroll
        for (int k4 = 0; k4 < 64; k4 += 4) {
            a0 += dotw(W0[k4],     xrow + k4 * 4);
            a1 += dotw(W0[k4 + 1], xrow + k4 * 4 + 4);
            a2 += dotw(W0[k4 + 2], xrow + k4 * 4 + 8);
            a3 += dotw(W0[k4 + 3], xrow + k4 * 4 + 12);
        }
        outv[lane * MEMD + base + lr] = (a0 + a1) + (a2 + a3);
    }
}

// ---------------- P0: fp32 pass + fp16 conversion (S_0, alpha_0) ----------------
__global__ void __launch_bounds__(256, 2)
k_bigc(const float* __restrict__ M) {
    __shared__ float cV1[8 * MEMD], cV2[8 * MEMD];
    __shared__ float cm1[8], cz1[8], cm2[8], cz2[8];

    const int b  = blockIdx.x / CPB;
    const int cb = blockIdx.x % CPB;
    const int rs = (cb * LDIM) / CPB;
    const int re = ((cb + 1) * LDIM) / CPB;
    const int t = threadIdx.x, w = t >> 5, k = t & 31;

    float4 z4 = make_float4(0.f, 0.f, 0.f, 0.f);
    const int bo = b * MEMD + 4 * k;
    float4 qb0 = *(const float4*)(g_qb + bo), qb1 = *(const float4*)(g_qb + bo + 128);
    float4 qa0 = *(const float4*)(g_qa + bo), qa1 = *(const float4*)(g_qa + bo + 128);

    const float* Mb = M + (size_t)b * LDIM * MEMD;
    uint2* Mhb = (uint2*)(g_Mh + (size_t)b * LDIM * 32);

    float m1 = -1e30f, z1 = 0.f, m2 = -1e30f, z2 = 0.f;
    float4 V10 = z4, V11 = z4, V20 = z4, V21 = z4;

    for (int r4 = rs + w * 4; r4 < re; r4 += 32) {
        float4 x[4][2];
        #pragma unroll
        for (int i = 0; i < 4; i++) {
            int row = r4 + i; if (row > re - 1) row = re - 1;
            const float4* rp = (const float4*)(Mb + (size_t)row * MEMD);
            x[i][0] = __ldg(rp + k);
            x[i][1] = __ldg(rp + 32 + k);
        }
        #pragma unroll
        for (int i = 0; i < 4; i++) {
            bool valid = (r4 + i) < re;
            if (valid) {
                __half2 h0 = __floats2half2_rn(x[i][0].x, x[i][0].y);
                __half2 h1 = __floats2half2_rn(x[i][0].z, x[i][0].w);
                __half2 h2 = __floats2half2_rn(x[i][1].x, x[i][1].y);
                __half2 h3 = __floats2half2_rn(x[i][1].z, x[i][1].w);
                uint2 u0, u1;
                u0.x = *(unsigned*)&h0; u0.y = *(unsigned*)&h1;
                u1.x = *(unsigned*)&h2; u1.y = *(unsigned*)&h3;
                Mhb[(size_t)(r4 + i) * 64 + k] = u0;
                Mhb[(size_t)(r4 + i) * 64 + 32 + k] = u1;
            }
            float db = dot44(qb0, x[i][0]) + dot44(qb1, x[i][1]);
            float da = dot44(qa0, x[i][0]) + dot44(qa1, x[i][1]);
            #pragma unroll
            for (int off = 16; off; off >>= 1) {
                db += __shfl_xor_sync(~0u, db, off);
                da += __shfl_xor_sync(~0u, da, off);
            }
            if (valid) {
                if (db > m1) {
                    float sc = __expf(m1 - db);
                    z1 *= sc; scale4(V10, sc); scale4(V11, sc); m1 = db;
                }
                float w1 = __expf(db - m1);
                z1 += w1; fma4(V10, w1, x[i][0]); fma4(V11, w1, x[i][1]);
                if (da > m2) {
                    float sc = __expf(m2 - da);
                    z2 *= sc; scale4(V20, sc); scale4(V21, sc); m2 = da;
                }
                float w2 = __expf(da - m2);
                z2 += w2; fma4(V20, w2, x[i][0]); fma4(V21, w2, x[i][1]);
                if (k == i) g_scoreS[b * LDIM + r4 + i] = db;   // plane 0
            }
        }
    }

    *(float4*)(cV1 + w * MEMD + 4 * k)       = V10;
    *(float4*)(cV1 + w * MEMD + 128 + 4 * k) = V11;
    *(float4*)(cV2 + w * MEMD + 4 * k)       = V20;
    *(float4*)(cV2 + w * MEMD + 128 + 4 * k) = V21;
    if (k == 0) { cm1[w] = m1; cz1[w] = z1; cm2[w] = m2; cz2[w] = z2; }
    __syncthreads();
    float a1 = cm1[0], a2 = cm2[0];
    #pragma unroll
    for (int wi = 1; wi < 8; wi++) { a1 = fmaxf(a1, cm1[wi]); a2 = fmaxf(a2, cm2[wi]); }
    float v1 = 0.f, gz1 = 0.f, v2 = 0.f, gz2 = 0.f;
    #pragma unroll
    for (int wi = 0; wi < 8; wi++) {
        float e1 = __expf(cm1[wi] - a1), e2 = __expf(cm2[wi] - a2);
        v1 += e1 * cV1[wi * MEMD + t]; gz1 += e1 * cz1[wi];
        v2 += e2 * cV2[wi * MEMD + t]; gz2 += e2 * cz2[wi];
    }
    int slot = blockIdx.x;
    g_pV1[slot * MEMD + t] = v1;
    g_pV2[slot * MEMD + t] = v2;
    if (t == 0) {
        g_pm1[slot] = a1; g_pz1[slot] = gz1;
        g_pm2[slot] = a2; g_pz2[slot] = gz2;
    }
}

// ---------------- P1..P5: fp16 streaming pass, scores only (no acc fused) ----------------
__global__ void __launch_bounds__(256, 2)
k_bigh(int doMain, int doEnd, int sP, int eP) {
    __shared__ float cV1[8 * MEMD], cV2[8 * MEMD];
    __shared__ float cm1[8], cz1[8], cm2[8], cz2[8], cmE[8], czE[8];

    const int b  = blockIdx.x / CPB;
    const int cb = blockIdx.x % CPB;
    const int rs = (cb * LDIM) / CPB;
    const int re = ((cb + 1) * LDIM) / CPB;
    const int t = threadIdx.x, w = t >> 5, k = t & 31;

    float4 z4 = make_float4(0.f, 0.f, 0.f, 0.f);
    float4 qb0 = z4, qb1 = z4, qa0 = z4, qa1 = z4, qe0 = z4, qe1 = z4;
    const int bo = b * MEMD + 8 * k;
    if (doMain) {
        qb0 = *(const float4*)(g_qb + bo); qb1 = *(const float4*)(g_qb + bo + 4);
        qa0 = *(const float4*)(g_qa + bo); qa1 = *(const float4*)(g_qa + bo + 4);
    }
    if (doEnd) {
        qe0 = *(const float4*)(g_qe + bo); qe1 = *(const float4*)(g_qe + bo + 4);
    }
    float* sWr = g_scoreS + (size_t)sP * OUT_HALF;
    float* eWr = g_scoreE + (size_t)eP * OUT_HALF;
    const uint4* Mhb = g_Mh + (size_t)b * LDIM * 32;

    float m1 = -1e30f, z1 = 0.f, m2 = -1e30f, z2 = 0.f, mE = -1e30f, zE = 0.f;
    float4 V10 = z4, V11 = z4, V20 = z4, V21 = z4;

    for (int r4 = rs + w * 4; r4 < re; r4 += 32) {
        uint4 xr[4];
        #pragma unroll
        for (int i = 0; i < 4; i++) {
            int row = r4 + i; if (row > re - 1) row = re - 1;
            xr[i] = __ldg(Mhb + (size_t)row * 32 + k);
        }
        #pragma unroll
        for (int i = 0; i < 4; i++) {
            bool valid = (r4 + i) < re;
            const __half2* h = (const __half2*)&xr[i];
            float2 f0 = __half22float2(h[0]);
            float2 f1 = __half22float2(h[1]);
            float2 f2 = __half22float2(h[2]);
            float2 f3 = __half22float2(h[3]);
            float4 x0 = make_float4(f0.x, f0.y, f1.x, f1.y);
            float4 x1 = make_float4(f2.x, f2.y, f3.x, f3.y);
            float db = 0.f, da = 0.f, de = 0.f;
            if (doMain) {
                db = dot44(qb0, x0) + dot44(qb1, x1);
                da = dot44(qa0, x0) + dot44(qa1, x1);
            }
            if (doEnd) de = dot44(qe0, x0) + dot44(qe1, x1);
            #pragma unroll
            for (int off = 16; off; off >>= 1) {
                db += __shfl_xor_sync(~0u, db, off);
                da += __shfl_xor_sync(~0u, da, off);
                de += __shfl_xor_sync(~0u, de, off);
            }
            if (doMain && valid) {
                if (db > m1) {
                    float sc = __expf(m1 - db);
                    z1 *= sc; scale4(V10, sc); scale4(V11, sc); m1 = db;
                }
                float w1 = __expf(db - m1);
                z1 += w1; fma4(V10, w1, x0); fma4(V11, w1, x1);
                if (da > m2) {
                    float sc = __expf(m2 - da);
                    z2 *= sc; scale4(V20, sc); scale4(V21, sc); m2 = da;
                }
                float w2 = __expf(da - m2);
                z2 += w2; fma4(V20, w2, x0); fma4(V21, w2, x1);
            }
            if (doEnd && valid) {
                if (de > mE) { zE *= __expf(mE - de); mE = de; }
                zE += __expf(de - mE);
            }
            if (valid && k == i) {
                int idx = b * LDIM + r4 + i;
                if (doMain) sWr[idx] = db;
                if (doEnd)  eWr[idx] = de;
            }
        }
    }

    if (k == 0) {
        cm1[w] = m1; cz1[w] = z1; cm2[w] = m2; cz2[w] = z2;
        cmE[w] = mE; czE[w] = zE;
    }
    if (doMain) {
        *(float4*)(cV1 + w * MEMD + 8 * k)     = V10;
        *(float4*)(cV1 + w * MEMD + 8 * k + 4) = V11;
        *(float4*)(cV2 + w * MEMD + 8 * k)     = V20;
        *(float4*)(cV2 + w * MEMD + 8 * k + 4) = V21;
    }
    __syncthreads();
    int slot = blockIdx.x;
    if (doMain) {
        float a1 = cm1[0], a2 = cm2[0];
        #pragma unroll
        for (int wi = 1; wi < 8; wi++) { a1 = fmaxf(a1, cm1[wi]); a2 = fmaxf(a2, cm2[wi]); }
        float v1 = 0.f, gz1 = 0.f, v2 = 0.f, gz2 = 0.f;
        #pragma unroll
        for (int wi = 0; wi < 8; wi++) {
            float e1 = __expf(cm1[wi] - a1), e2 = __expf(cm2[wi] - a2);
            v1 += e1 * cV1[wi * MEMD + t]; gz1 += e1 * cz1[wi];
            v2 += e2 * cV2[wi * MEMD + t]; gz2 += e2 * cz2[wi];
        }
        g_pV1[slot * MEMD + t] = v1;
        g_pV2[slot * MEMD + t] = v2;
        if (t == 0) {
            g_pm1[slot] = a1; g_pz1[slot] = gz1;
            g_pm2[slot] = a2; g_pz2[slot] = gz2;
        }
    }
    if (doEnd && t == 0) {
        float aE = cmE[0];
        #pragma unroll
        for (int wi = 1; wi < 8; wi++) aE = fmaxf(aE, cmE[wi]);
        float gzE = 0.f;
        #pragma unroll
        for (int wi = 0; wi < 8; wi++) gzE += __expf(cmE[wi] - aE) * czE[wi];
        g_pmE[slot] = aE; g_pzE[slot] = gzE;
    }
}

// ---------------- fused turn tail: gemv (qe/gates + stats) -> grid barrier -> GRU + qb/qa ----------------
// grid 56, 256 thr. Phase A: CTA 0-7 qe rows; 8-31 W_ih; 32-55 W_hh.
// Phase B (CTA 0-15 only, after software barrier): GRU + staged qb/qa.
__global__ void __launch_bounds__(256)
k_tail(const float* __restrict__ We,
       const float* __restrict__ W_ih,
       const float* __restrict__ W_hh,
       const float* __restrict__ b_ih,
       const float* __restrict__ b_hh,
       const float* __restrict__ Wb,
       const float* __restrict__ Wa,
       int turn, int sp) {
    extern __shared__ float smg[];
    float* xs = smg;                  // 32*257
    float* es = smg + 8224;           // 32*257 (seg0)
    float* ws = smg + 16448;          // 8192 staged weights
    __shared__ float wg[32 * 10];
    __shared__ unsigned stk;

    const int cta = blockIdx.x, t = threadIdx.x, w = t >> 5, lane = t & 31;
    const int seg = (cta < 8) ? 0 : (cta < 32 ? 1 : 2);
    const float* sbase = g_s + sp * (BATCH * MEMD);

    // merge weights (seg0: start-softmax partials; seg1: alpha partials)
    if (t < 32 && seg != 2) {
        int b = t;
        const float* pm = (seg == 0) ? g_pm1 : g_pm2;
        const float* pz = (seg == 0) ? g_pz1 : g_pz2;
        float m = -1e30f;
        #pragma unroll
        for (int c = 0; c < CPB; c++) m = fmaxf(m, pm[b * CPB + c]);
        float Z = 0.f;
        #pragma unroll
        for (int c = 0; c < CPB; c++) {
            float e = __expf(pm[b * CPB + c] - m);
            wg[b * 10 + c] = e;
            Z += e * pz[b * CPB + c];
        }
        wg[b * 10 + 9] = 1.f / Z;
        if (cta == 0) {
            g_stSm[turn * 32 + b] = m; g_stSrz[turn * 32 + b] = 1.f / Z;
            if (turn > 0) {
                float mE = -1e30f;
                #pragma unroll
                for (int c = 0; c < CPB; c++) mE = fmaxf(mE, g_pmE[b * CPB + c]);
                float ZE = 0.f;
                #pragma unroll
                for (int c = 0; c < CPB; c++) ZE += __expf(g_pmE[b * CPB + c] - mE) * g_pzE[b * CPB + c];
                g_stEm[(turn - 1) * 32 + b] = mE;
                g_stErz[(turn - 1) * 32 + b] = 1.f / ZE;
            }
        }
    }
    __syncthreads();

    // input vectors
    if (seg == 0) {
        for (int i = t; i < BATCH * MEMD; i += 256) {
            int b = i >> 8, j = i & 255;
            xs[b * 257 + j] = sbase[i];
            float v = 0.f;
            #pragma unroll
            for (int c = 0; c < CPB; c++)
                v += wg[b * 10 + c] * g_pV1[(b * CPB + c) * MEMD + j];
            es[b * 257 + j] = v * wg[b * 10 + 9];
        }
    } else if (seg == 1) {
        for (int i = t; i < BATCH * MEMD; i += 256) {
            int b = i >> 8, j = i & 255;
            float v = 0.f;
            #pragma unroll
            for (int c = 0; c < CPB; c++)
                v += wg[b * 10 + c] * g_pV2[(b * CPB + c) * MEMD + j];
            xs[b * 257 + j] = v * wg[b * 10 + 9];
        }
    } else {
        for (int i = t; i < BATCH * MEMD; i += 256)
            xs[(i >> 8) * 257 + (i & 255)] = sbase[i];
    }
    __syncthreads();

    {
        const float* xrow = &xs[lane * 257];
        const float* erow = &es[lane * 257];
        const float4* ws4 = (const float4*)ws;

        if (seg == 0) {
            int base = cta * 32;
            for (int ch = 0; ch < 2; ch++) {
                for (int i = t; i < 8192; i += 256)
                    ws[i] = We[(size_t)(base + ch * 16 + (i >> 9)) * 512 + (i & 511)];
                __syncthreads();
                #pragma unroll
                for (int rr = 0; rr < 2; rr++) {
                    int lr = w * 2 + rr;
                    int r = base + ch * 16 + lr;
                    const float4* W0 = ws4 + lr * 128;
                    float a0 = 0.f, a1 = 0.f, a2 = 0.f, a3 = 0.f;
                    #pragma unroll
                    for (int k4 = 0; k4 < 64; k4 += 4) {
                        a0 += dotw(W0[k4],     xrow + k4 * 4);
                        a1 += dotw(W0[k4 + 1], xrow + k4 * 4 + 4);
                        a2 += dotw(W0[k4 + 2], xrow + k4 * 4 + 8);
                        a3 += dotw(W0[k4 + 3], xrow + k4 * 4 + 12);
                    }
                    #pragma unroll
                    for (int k4 = 0; k4 < 64; k4 += 4) {
                        a0 += dotw(W0[64 + k4],     erow + k4 * 4);
                        a1 += dotw(W0[64 + k4 + 1], erow + k4 * 4 + 4);
                        a2 += dotw(W0[64 + k4 + 2], erow + k4 * 4 + 8);
                        a3 += dotw(W0[64 + k4 + 3], erow + k4 * 4 + 12);
                    }
                    g_qe[lane * MEMD + r] = (a0 + a1) + (a2 + a3);
                }
                __syncthreads();
            }
        } else {
            const float* W = (seg == 1) ? W_ih : W_hh;
            const float* bias = (seg == 1) ? b_ih : b_hh;
            float* gout = (seg == 1) ? g_gio : g_gho;
            int base = ((seg == 1) ? (cta - 8) : (cta - 32)) * 32;
            for (int i = t; i < 8192; i += 256)
                ws[i] = W[(size_t)(base + (i >> 8)) * 256 + (i & 255)];
            __syncthreads();
            #pragma unroll
            for (int rr = 0; rr < 4; rr++) {
                int lr = w * 4 + rr;
                int ri = base + lr;
                const float4* W0 = ws4 + lr * 64;
                float a0 = __ldg(bias + ri), a1 = 0.f, a2 = 0.f, a3 = 0.f;
                #pragma unroll
                for (int k4 = 0; k4 < 64; k4 += 4) {
                    a0 += dotw(W0[k4],     xrow + k4 * 4);
                    a1 += dotw(W0[k4 + 1], xrow + k4 * 4 + 4);
                    a2 += dotw(W0[k4 + 2], xrow + k4 * 4 + 8);
                    a3 += dotw(W0[k4 + 3], xrow + k4 * 4 + 12);
                }
                gout[ri * 32 + lane] = (a0 + a1) + (a2 + a3);
            }
        }
    }

    // ---- software grid barrier (monotonic ticket; all 56 CTAs resident) ----
    __syncthreads();
    __threadfence();
    if (t == 0) stk = atomicAdd(&g_barrier, 1u);
    __syncthreads();
    if (cta >= 16) return;
    unsigned target = (stk / 56u + 1u) * 56u;
    if (t == 0) {
        while (atomicAdd(&g_barrier, 0u) < target) { }
    }
    __syncthreads();
    __threadfence();

    // ---- phase B: GRU (redundant per CTA) + qb/qa slice ----
    const float* sOld = sbase;
    float* sNew = g_s + (1 - sp) * (BATCH * MEMD);
    for (int i = t; i < BATCH * MEMD; i += 256) {
        int col = i >> 5, b = i & 31;
        float gir = g_gio[i], giz = g_gio[8192 + i], gin = g_gio[16384 + i];
        float ghr = g_gho[i], ghz = g_gho[8192 + i], ghn = g_gho[16384 + i];
        float r = 1.0f / (1.0f + __expf(-(gir + ghr)));
        float z = 1.0f / (1.0f + __expf(-(giz + ghz)));
        float n = tanhf(gin + r * ghn);
        float sold = sOld[b * MEMD + col];
        float sv = (1.0f - z) * n + z * sold;
        xs[b * 257 + col] = sv;
        if (cta == 0) sNew[b * MEMD + col] = sv;
    }
    float* ws2 = smg + 8224;
    const float* W = (cta < 8) ? Wb : Wa;
    int base = (cta & 7) * 32;
    for (int i = t; i < 8192; i += 256)
        ws2[i] = W[(size_t)(base + (i >> 8)) * 256 + (i & 255)];
    __syncthreads();
    const float* xrow = &xs[lane * 257];
    const float4* ws4 = (const float4*)ws2;
    float* outv = (cta < 8) ? g_qb : g_qa;
    #pragma unroll
    for (int rr = 0; rr < 4; rr++) {
        int lr = w * 4 + rr;
        const float4* W0 = ws4 + lr * 64;
        float a0 = 0.f, a1 = 0.f, a2 = 0.f, a3 = 0.f;
        #pragma unroll
        for (int k4 = 0; k4 < 64; k4 += 4) {
            a0 += dotw(W0[k4],     xrow + k4 * 4);
            a1 += dotw(W0[k4 + 1], xrow + k4 * 4 + 4);
            a2 += dotw(W0[k4 + 2], xrow + k4 * 4 + 8);
            a3 += dotw(W0[k4 + 3], xrow + k4 * 4 + 12);
        }
        outv[lane * MEMD + base + lr] = (a0 + a1) + (a2 + a3);
    }
}

// ---------------- finalize: log-mean over 5 score planes per half ----------------
// grid (128, 2), 256 thr, 4 elements/thread (float4).
__global__ void k_fin(float* __restrict__ out) {
    int half = blockIdx.y;
    int gbase = blockIdx.x * 1024;
    int b = blockIdx.x >> 2;
    __shared__ float sE4[2];
    float m[5], rz[5];
    if (half == 0) {
        #pragma unroll
        for (int tt = 0; tt < 5; tt++) {
            m[tt] = g_stSm[tt * 32 + b]; rz[tt] = g_stSrz[tt * 32 + b];
        }
    } else {
        #pragma unroll
        for (int tt = 0; tt < 4; tt++) {
            m[tt] = g_stEm[tt * 32 + b]; rz[tt] = g_stErz[tt * 32 + b];
        }
        if (threadIdx.x == 0) {
            float mE = -1e30f;
            #pragma unroll
            for (int c = 0; c < CPB; c++) mE = fmaxf(mE, g_pmE[b * CPB + c]);
            float ZE = 0.f;
            #pragma unroll
            for (int c = 0; c < CPB; c++) ZE += __expf(g_pmE[b * CPB + c] - mE) * g_pzE[b * CPB + c];
            sE4[0] = mE; sE4[1] = 1.f / ZE;
        }
        __syncthreads();
        m[4] = sE4[0]; rz[4] = sE4[1];
    }
    const float* basep = half ? g_scoreE : g_scoreS;
    int idx = gbase + threadIdx.x * 4;
    float4 acc = make_float4(0.f, 0.f, 0.f, 0.f);
    #pragma unroll
    for (int tt = 0; tt < 5; tt++) {
        float4 s = *(const float4*)(basep + (size_t)tt * OUT_HALF + idx);
        acc.x += __expf(s.x - m[tt]) * rz[tt];
        acc.y += __expf(s.y - m[tt]) * rz[tt];
        acc.z += __expf(s.z - m[tt]) * rz[tt];
        acc.w += __expf(s.w - m[tt]) * rz[tt];
    }
    float4 o;
    o.x = logf(acc.x * 0.2f);
    o.y = logf(acc.y * 0.2f);
    o.z = logf(acc.z * 0.2f);
    o.w = logf(acc.w * 0.2f);
    *(float4*)(out + (size_t)half * OUT_HALF + idx) = o;
}

// ---------------- launch ----------------
extern "C" void kernel_launch(void* const* d_in, const int* in_sizes, int n_in,
                              void* d_out, int out_size) {
    (void)in_sizes; (void)n_in; (void)out_size;
    const float* M    = (const float*)d_in[0];
    const float* s0   = (const float*)d_in[1];
    const float* Wb   = (const float*)d_in[2];
    const float* We   = (const float*)d_in[3];
    const float* Wa   = (const float*)d_in[4];
    const float* W_ih = (const float*)d_in[5];
    const float* W_hh = (const float*)d_in[6];
    const float* b_ih = (const float*)d_in[7];
    const float* b_hh = (const float*)d_in[8];
    float* out = (float*)d_out;

    const int TAIL_SMEM = (2 * 8224 + 8192) * 4;   // 98,560 B
    const int INIT_SMEM = (8224 + 8192) * 4;       // 65,664 B
    cudaFuncSetAttribute(k_tail,   cudaFuncAttributeMaxDynamicSharedMemorySize, TAIL_SMEM);
    cudaFuncSetAttribute(k_initvm, cudaFuncAttributeMaxDynamicSharedMemorySize, INIT_SMEM);

    k_initvm<<<16, 256, INIT_SMEM>>>(s0, Wb, Wa);                              // 0
    k_bigc<<<G_CTAS, 256>>>(M);                                                // 1: S0,a0
    k_tail<<<56, 256, TAIL_SMEM>>>(We, W_ih, W_hh, b_ih, b_hh, Wb, Wa, 0, 0);  // 2
    k_bigh<<<G_CTAS, 256>>>(1, 1, 1, 0);                                       // 3: S1,a1,E0  <-- ncu
    k_tail<<<56, 256, TAIL_SMEM>>>(We, W_ih, W_hh, b_ih, b_hh, Wb, Wa, 1, 1);  // 4
    k_bigh<<<G_CTAS, 256>>>(1, 1, 2, 1);                                       // 5: S2,a2,E1
    k_tail<<<56, 256, TAIL_SMEM>>>(We, W_ih, W_hh, b_ih, b_hh, Wb, Wa, 2, 0);  // 6
    k_bigh<<<G_CTAS, 256>>>(1, 1, 3, 2);                                       // 7: S3,a3,E2
    k_tail<<<56, 256, TAIL_SMEM>>>(We, W_ih, W_hh, b_ih, b_hh, Wb, Wa, 3, 1);  // 8
    k_bigh<<<G_CTAS, 256>>>(1, 1, 4, 3);                                       // 9: S4,a4,E3
    k_tail<<<56, 256, TAIL_SMEM>>>(We, W_ih, W_hh, b_ih, b_hh, Wb, Wa, 4, 0);  // 10: stats S4,E3 + qe4
    k_bigh<<<G_CTAS, 256>>>(0, 1, 0, 4);                                       // 11: E4 only
    k_fin<<<dim3(128, 2), 256>>>(out);                                         // 12
}